// round 15
// baseline (speedup 1.0000x reference)
#include <cuda_runtime.h>

// Flow-warp bilinear, direct scalar gather, 2 y-adjacent pixels per thread,
// channels pair-batched (16 taps in flight before compute). Channel loop
// split across 2 CTAs (8 channels each) to double CTA count -> finer wave
// granularity (6.9 waves vs 3.46), shrinking the partial-wave tail.
// out[b,c,y,x] = bilerp(src[b,c], clamp(y+flow[b,0,y,x]), clamp(x+flow[b,1,y,x]))
// B=8, C=16, H=W=512.
// Edge trick: clamp x0,y0 <= 510; when floor==511 the fractional weight is
// exactly 1.0 so the result is identical and the +1 taps stay in bounds.

#define B_ 8
#define C_ 16
#define H_ 512
#define W_ 512
#define HW_ (H_ * W_)
#define CHW_ (C_ * HW_)
#define CPT_ 8   // channels per thread (C_ / 2)

__global__ void __launch_bounds__(256, 6) warp_gather2h_kernel(
    const float* __restrict__ src,
    const float* __restrict__ flow,
    float* __restrict__ out)
{
    int idx = blockIdx.x * blockDim.x + threadIdx.x;   // over B * H/2 * W
    int x   = idx & (W_ - 1);
    int ry  = (idx >> 9) & 255;
    int b   = idx >> 17;
    int y   = ry * 2;
    int ch0 = blockIdx.y * CPT_;                        // 0 or 8

    const float* __restrict__ fby = flow + b * 2 * HW_;
    const float* __restrict__ fbx = fby + HW_;

    int   g00[2];
    float wxv[2], wyv[2];

#pragma unroll
    for (int k = 0; k < 2; ++k) {
        int yy = y + k;
        int fo = yy * W_ + x;
        float fy = __ldcs(fby + fo);            // read-once per CTA: stream
        float fx = __ldcs(fbx + fo);
        // reference's normalize->unnormalize cancels exactly
        float py = fminf(fmaxf((float)yy + fy, 0.0f), (float)(H_ - 1));
        float px = fminf(fmaxf((float)x  + fx, 0.0f), (float)(W_ - 1));
        float y0f = floorf(py);
        float x0f = floorf(px);
        int y0 = min((int)y0f, H_ - 2);         // edge: weight becomes exactly 1
        int x0 = min((int)x0f, W_ - 2);
        wyv[k] = py - (float)y0;
        wxv[k] = px - (float)x0;
        g00[k] = (y0 << 9) + x0;
    }

    const float* __restrict__ sb = src + b * CHW_ + ch0 * HW_;
    float* __restrict__ ob = out + b * CHW_ + ch0 * HW_ + y * W_ + x;

    const int gA = g00[0];
    const int gB = g00[1];

#pragma unroll
    for (int c = 0; c < CPT_; c += 2) {
        const float* __restrict__ sc0 = sb + c * HW_;
        const float* __restrict__ sc1 = sc0 + HW_;

        // ---- issue all 16 gathers for two channels up front ----
        float a00 = __ldg(sc0 + gA);
        float a01 = __ldg(sc0 + gA + 1);
        float a10 = __ldg(sc0 + gA + W_);
        float a11 = __ldg(sc0 + gA + W_ + 1);
        float b00 = __ldg(sc0 + gB);
        float b01 = __ldg(sc0 + gB + 1);
        float b10 = __ldg(sc0 + gB + W_);
        float b11 = __ldg(sc0 + gB + W_ + 1);

        float c00 = __ldg(sc1 + gA);
        float c01 = __ldg(sc1 + gA + 1);
        float c10 = __ldg(sc1 + gA + W_);
        float c11 = __ldg(sc1 + gA + W_ + 1);
        float d00 = __ldg(sc1 + gB);
        float d01 = __ldg(sc1 + gB + 1);
        float d10 = __ldg(sc1 + gB + W_);
        float d11 = __ldg(sc1 + gB + W_ + 1);

        // ---- compute + streaming stores ----
        float atop = fmaf(wxv[0], a01 - a00, a00);
        float abot = fmaf(wxv[0], a11 - a10, a10);
        float btop = fmaf(wxv[1], b01 - b00, b00);
        float bbot = fmaf(wxv[1], b11 - b10, b10);

        float ctop = fmaf(wxv[0], c01 - c00, c00);
        float cbot = fmaf(wxv[0], c11 - c10, c10);
        float dtop = fmaf(wxv[1], d01 - d00, d00);
        float dbot = fmaf(wxv[1], d11 - d10, d10);

        float* __restrict__ oc0 = ob + c * HW_;
        float* __restrict__ oc1 = oc0 + HW_;
        __stcs(oc0,      fmaf(wyv[0], abot - atop, atop));
        __stcs(oc0 + W_, fmaf(wyv[1], bbot - btop, btop));
        __stcs(oc1,      fmaf(wyv[0], cbot - ctop, ctop));
        __stcs(oc1 + W_, fmaf(wyv[1], dbot - dtop, dtop));
    }
}

extern "C" void kernel_launch(void* const* d_in, const int* in_sizes, int n_in,
                              void* d_out, int out_size)
{
    const float* src  = (const float*)d_in[0];
    const float* flow = (const float*)d_in[1];
    float* out        = (float*)d_out;

    const int total = B_ * (H_ / 2) * W_;   // 1,048,576 threads
    dim3 grid(total / 256, C_ / CPT_, 1);   // 4096 x 2 = 8192 CTAs
    warp_gather2h_kernel<<<grid, 256>>>(src, flow, out);
}

// round 16
// speedup vs baseline: 1.0058x; 1.0058x over previous
#include <cuda_runtime.h>

// FINAL: Flow-warp bilinear, direct scalar gather, 2 y-adjacent pixels per
// thread, channels pair-batched (16 taps in flight before any compute).
// Measured optimum across 15 structural variants (smem tiling, vector loads,
// persistent grids, RPT/occupancy sweep, cache policies, wave splitting).
// l1tex gather wavefronts are the binding resource at ~85% busy = the
// effective ceiling for this scatter pattern on sm_103a.
// Carveout hint maximizes L1D (no smem used) for tap line reuse.
// out[b,c,y,x] = bilerp(src[b,c], clamp(y+flow[b,0,y,x]), clamp(x+flow[b,1,y,x]))
// B=8, C=16, H=W=512.
// Edge trick: clamp x0,y0 <= 510; when floor==511 the fractional weight is
// exactly 1.0 so the result is identical and the +1 taps stay in bounds.

#define B_ 8
#define C_ 16
#define H_ 512
#define W_ 512
#define HW_ (H_ * W_)
#define CHW_ (C_ * HW_)

__global__ void __launch_bounds__(256, 6) warp_gather_final_kernel(
    const float* __restrict__ src,
    const float* __restrict__ flow,
    float* __restrict__ out)
{
    int idx = blockIdx.x * blockDim.x + threadIdx.x;   // over B * H/2 * W
    int x   = idx & (W_ - 1);
    int ry  = (idx >> 9) & 255;
    int b   = idx >> 17;
    int y   = ry * 2;

    const float* __restrict__ fby = flow + b * 2 * HW_;
    const float* __restrict__ fbx = fby + HW_;

    int   g00[2];
    float wxv[2], wyv[2];

#pragma unroll
    for (int k = 0; k < 2; ++k) {
        int yy = y + k;
        int fo = yy * W_ + x;
        float fy = __ldcs(fby + fo);            // read-once: stream
        float fx = __ldcs(fbx + fo);
        // reference's normalize->unnormalize cancels exactly
        float py = fminf(fmaxf((float)yy + fy, 0.0f), (float)(H_ - 1));
        float px = fminf(fmaxf((float)x  + fx, 0.0f), (float)(W_ - 1));
        float y0f = floorf(py);
        float x0f = floorf(px);
        int y0 = min((int)y0f, H_ - 2);         // edge: weight becomes exactly 1
        int x0 = min((int)x0f, W_ - 2);
        wyv[k] = py - (float)y0;
        wxv[k] = px - (float)x0;
        g00[k] = (y0 << 9) + x0;
    }

    const float* __restrict__ sb = src + b * CHW_;
    float* __restrict__ ob = out + b * CHW_ + y * W_ + x;

    const int gA = g00[0];
    const int gB = g00[1];

#pragma unroll
    for (int c = 0; c < C_; c += 2) {
        const float* __restrict__ sc0 = sb + c * HW_;
        const float* __restrict__ sc1 = sc0 + HW_;

        // ---- issue all 16 gathers for two channels up front ----
        float a00 = __ldg(sc0 + gA);
        float a01 = __ldg(sc0 + gA + 1);
        float a10 = __ldg(sc0 + gA + W_);
        float a11 = __ldg(sc0 + gA + W_ + 1);
        float b00 = __ldg(sc0 + gB);
        float b01 = __ldg(sc0 + gB + 1);
        float b10 = __ldg(sc0 + gB + W_);
        float b11 = __ldg(sc0 + gB + W_ + 1);

        float c00 = __ldg(sc1 + gA);
        float c01 = __ldg(sc1 + gA + 1);
        float c10 = __ldg(sc1 + gA + W_);
        float c11 = __ldg(sc1 + gA + W_ + 1);
        float d00 = __ldg(sc1 + gB);
        float d01 = __ldg(sc1 + gB + 1);
        float d10 = __ldg(sc1 + gB + W_);
        float d11 = __ldg(sc1 + gB + W_ + 1);

        // ---- compute + streaming stores ----
        float atop = fmaf(wxv[0], a01 - a00, a00);
        float abot = fmaf(wxv[0], a11 - a10, a10);
        float btop = fmaf(wxv[1], b01 - b00, b00);
        float bbot = fmaf(wxv[1], b11 - b10, b10);

        float ctop = fmaf(wxv[0], c01 - c00, c00);
        float cbot = fmaf(wxv[0], c11 - c10, c10);
        float dtop = fmaf(wxv[1], d01 - d00, d00);
        float dbot = fmaf(wxv[1], d11 - d10, d10);

        float* __restrict__ oc0 = ob + c * HW_;
        float* __restrict__ oc1 = oc0 + HW_;
        __stcs(oc0,      fmaf(wyv[0], abot - atop, atop));
        __stcs(oc0 + W_, fmaf(wyv[1], bbot - btop, btop));
        __stcs(oc1,      fmaf(wyv[0], cbot - ctop, ctop));
        __stcs(oc1 + W_, fmaf(wyv[1], dbot - dtop, dtop));
    }
}

extern "C" void kernel_launch(void* const* d_in, const int* in_sizes, int n_in,
                              void* d_out, int out_size)
{
    const float* src  = (const float*)d_in[0];
    const float* flow = (const float*)d_in[1];
    float* out        = (float*)d_out;

    // No smem used: ask for the full 228KB L1D carveout (idempotent, capture-safe).
    cudaFuncSetAttribute(warp_gather_final_kernel,
                         cudaFuncAttributePreferredSharedMemoryCarveout, 0);

    const int total = B_ * (H_ / 2) * W_;   // 1,048,576 threads
    warp_gather_final_kernel<<<total / 256, 256>>>(src, flow, out);
}